// round 1
// baseline (speedup 1.0000x reference)
#include <cuda_runtime.h>

#define NQ     1224
#define TWOQ   2448
#define SMAX   50
#define BATCHN 1024
#define ROWS   (BATCHN * (SMAX - 1))   // 50176 (b, t) pairs, t = 1..49
#define VEC4   (TWOQ / 4)              // 612 float4 per batch row
#define WARPS_PER_BLOCK 8
#define THREADS (WARPS_PER_BLOCK * 32)

__global__ void init_out_kernel(float* out) {
    if (threadIdx.x == 0) out[0] = 0.0f;
}

__global__ __launch_bounds__(THREADS)
void loss_kernel(const float* __restrict__ pred,
                 const float* __restrict__ batch,
                 float* __restrict__ out) {
    __shared__ float warp_part[WARPS_PER_BLOCK];

    const int wid  = threadIdx.x >> 5;
    const int lane = threadIdx.x & 31;
    const int row  = blockIdx.x * WARPS_PER_BLOCK + wid;

    float contrib = 0.0f;

    if (row < ROWS) {
        const int b = row / (SMAX - 1);
        const int t = row - b * (SMAX - 1) + 1;          // 1..49 (delta step)
        const float4* rp =
            (const float4*)(batch + ((size_t)b * SMAX + t) * TWOQ);

        // Scan the 2448-col row for the single nonzero (one-hot).
        // 2 float4 loads per lane per iteration (256 floats / warp-iter),
        // warp-uniform early exit once found.
        int loc = -1;
        #pragma unroll 1
        for (int c = 0; c < VEC4; c += 64) {
            const int i0 = c + lane;        // always < 612 (max 607)
            const int i1 = i0 + 32;
            float4 v0 = rp[i0];
            float4 v1 = make_float4(0.f, 0.f, 0.f, 0.f);
            if (i1 < VEC4) v1 = rp[i1];

            if      (v0.x != 0.0f) loc = i0 * 4 + 0;
            else if (v0.y != 0.0f) loc = i0 * 4 + 1;
            else if (v0.z != 0.0f) loc = i0 * 4 + 2;
            else if (v0.w != 0.0f) loc = i0 * 4 + 3;
            else if (v1.x != 0.0f) loc = i1 * 4 + 0;
            else if (v1.y != 0.0f) loc = i1 * 4 + 1;
            else if (v1.z != 0.0f) loc = i1 * 4 + 2;
            else if (v1.w != 0.0f) loc = i1 * 4 + 3;

            if (__ballot_sync(0xffffffffu, loc >= 0)) break;
        }

        const int j = __reduce_max_sync(0xffffffffu, loc);

        if (lane == 0 && j >= 0) {
            // j < NQ  -> answered correctly (a=1), question index j
            // j >= NQ -> answered incorrectly (a=0), question index j-NQ
            const int  q = (j < NQ) ? j : (j - NQ);
            const float p =
                __ldg(&pred[((size_t)b * SMAX + (t - 1)) * NQ + q]);
            if (p > 0.0f) {
                // -(a*log(p) + (1-a)*log(1-p)) with a in {0,1}
                const float x = (j < NQ) ? p : (1.0f - p);
                contrib = -logf(x);
            }
        }
    }

    if (lane == 0) warp_part[wid] = contrib;
    __syncthreads();

    if (threadIdx.x == 0) {
        float s = 0.0f;
        #pragma unroll
        for (int w = 0; w < WARPS_PER_BLOCK; ++w) s += warp_part[w];
        atomicAdd(out, s);
    }
}

extern "C" void kernel_launch(void* const* d_in, const int* in_sizes, int n_in,
                              void* d_out, int out_size) {
    const float* pred  = (const float*)d_in[0];
    const float* batch = (const float*)d_in[1];
    float* out = (float*)d_out;

    init_out_kernel<<<1, 32>>>(out);

    const int grid = (ROWS + WARPS_PER_BLOCK - 1) / WARPS_PER_BLOCK; // 6272
    loss_kernel<<<grid, THREADS>>>(pred, batch, out);
}

// round 2
// speedup vs baseline: 1.0699x; 1.0699x over previous
#include <cuda_runtime.h>

#define NQ     1224
#define TWOQ   2448
#define SMAX   50
#define BATCHN 1024
#define ROWS   (BATCHN * (SMAX - 1))   // 50176 (b, t) pairs, t = 1..49
#define VEC4   (TWOQ / 4)              // 612 float4 per batch row
#define WARPS_PER_BLOCK 8
#define THREADS (WARPS_PER_BLOCK * 32)

__global__ void init_out_kernel(float* out) {
    if (threadIdx.x == 0) out[0] = 0.0f;
}

__device__ __forceinline__ unsigned nz4(const float4& v) {
    return __float_as_uint(v.x) | __float_as_uint(v.y) |
           __float_as_uint(v.z) | __float_as_uint(v.w);
}

__device__ __forceinline__ int locate4(const float4& v, int i) {
    int base = i * 4;
    if (v.x != 0.0f) return base;
    if (v.y != 0.0f) return base + 1;
    if (v.z != 0.0f) return base + 2;
    return base + 3;
}

__global__ __launch_bounds__(THREADS)
void loss_kernel(const float* __restrict__ pred,
                 const float* __restrict__ batch,
                 float* __restrict__ out) {
    __shared__ float warp_part[WARPS_PER_BLOCK];

    const int wid  = threadIdx.x >> 5;
    const int lane = threadIdx.x & 31;
    const int row  = blockIdx.x * WARPS_PER_BLOCK + wid;

    float contrib = 0.0f;

    if (row < ROWS) {
        const int b = row / (SMAX - 1);
        const int t = row - b * (SMAX - 1) + 1;          // 1..49 (delta step)
        const float4* rp =
            (const float4*)(batch + ((size_t)b * SMAX + t) * TWOQ);

        // Scan the 2448-col row for the single nonzero (one-hot).
        // 4 float4 loads per lane per iteration (512 floats / warp-iter):
        // deep MLP to cover DRAM latency, warp-uniform early exit.
        int loc = -1;
        #pragma unroll 1
        for (int c = 0; c < VEC4; c += 128) {
            const int i0 = c + lane;        // max 543  < 612
            const int i1 = i0 + 32;         // max 575  < 612
            const int i2 = i0 + 64;         // max 607  < 612
            const int i3 = i0 + 96;         // max 639 -> guard
            const float4 z = make_float4(0.f, 0.f, 0.f, 0.f);
            float4 v0 = rp[i0];
            float4 v1 = rp[i1];
            float4 v2 = rp[i2];
            float4 v3 = (i3 < VEC4) ? rp[i3] : z;

            // cheap any-nonzero test: values are exactly 0.0f or 1.0f,
            // so integer OR of the raw bits is exact.
            const unsigned a0 = nz4(v0);
            const unsigned a1 = nz4(v1);
            const unsigned a2 = nz4(v2);
            const unsigned a3 = nz4(v3);

            if (__ballot_sync(0xffffffffu, a0 | a1 | a2 | a3)) {
                // decode exact position only on the exit path
                if      (a0) loc = locate4(v0, i0);
                else if (a1) loc = locate4(v1, i1);
                else if (a2) loc = locate4(v2, i2);
                else if (a3) loc = locate4(v3, i3);
                break;
            }
        }

        const int j = __reduce_max_sync(0xffffffffu, loc);

        if (lane == 0 && j >= 0) {
            // j < NQ  -> answered correctly (a=1), question index j
            // j >= NQ -> answered incorrectly (a=0), question index j-NQ
            const int  q = (j < NQ) ? j : (j - NQ);
            const float p =
                __ldg(&pred[((size_t)b * SMAX + (t - 1)) * NQ + q]);
            if (p > 0.0f) {
                // -(a*log(p) + (1-a)*log(1-p)) with a in {0,1}
                const float x = (j < NQ) ? p : (1.0f - p);
                contrib = -logf(x);
            }
        }
    }

    if (lane == 0) warp_part[wid] = contrib;
    __syncthreads();

    if (threadIdx.x == 0) {
        float s = 0.0f;
        #pragma unroll
        for (int w = 0; w < WARPS_PER_BLOCK; ++w) s += warp_part[w];
        atomicAdd(out, s);
    }
}

extern "C" void kernel_launch(void* const* d_in, const int* in_sizes, int n_in,
                              void* d_out, int out_size) {
    const float* pred  = (const float*)d_in[0];
    const float* batch = (const float*)d_in[1];
    float* out = (float*)d_out;

    init_out_kernel<<<1, 32>>>(out);

    const int grid = (ROWS + WARPS_PER_BLOCK - 1) / WARPS_PER_BLOCK; // 6272
    loss_kernel<<<grid, THREADS>>>(pred, batch, out);
}